// round 1
// baseline (speedup 1.0000x reference)
#include <cuda_runtime.h>

// Problem constants
#define S_LEN   2048
#define DH      64
#define BM      64
#define BN      64
#define PAD     68          // float stride for padded smem rows (16B-aligned, bank-diverse)
#define HEADS   16
#define BATCH   2
#define DMODEL  1024

// Intermediate attention output x = vals.reshape(B,S,DMODEL)  (16 MB)
__device__ float g_x[BATCH * S_LEN * DMODEL];

// ---------------------------------------------------------------------------
// Flash attention: grid (S/BM, B*H), 256 threads.
// Per CTA: 64 queries of one (b,h). Q/K/V slabs are contiguous [S,64] at
// base = (b*H+h)*S*DH thanks to the reference's direct reshape.
// ---------------------------------------------------------------------------
__global__ __launch_bounds__(256, 2)
void attn_kernel(const float* __restrict__ Q, const float* __restrict__ K,
                 const float* __restrict__ V, const float* __restrict__ mask)
{
    extern __shared__ float sm[];
    float* sQ   = sm;               // [BM][PAD]  (m,k) Q tile, pre-scaled
    float* sKT  = sQ  + BM * PAD;   // [DH][PAD]  (k,n) K transposed
    float* sV   = sKT + DH * PAD;   // [BN][PAD]  (k,n) V natural
    float* sP   = sV  + BN * PAD;   // [BM][PAD]  scores -> probs
    float* sM   = sP  + BM * PAD;   // [BM] running max
    float* sL   = sM  + BM;         // [BM] running denom
    float* sC   = sL  + BM;         // [BM] correction factor
    float* sRed = sC  + BM;         // [BM*4] partial reductions

    const int tid = threadIdx.x;
    const int tx  = tid & 15;       // micro-tile col group
    const int ty  = tid >> 4;       // micro-tile row group
    const int q0  = blockIdx.x * BM;
    const size_t base = (size_t)blockIdx.y * (S_LEN * DH);

    // ---- load Q tile, scaled by 1/sqrt(64) ----
    {
        const float scale = 0.125f;
        #pragma unroll
        for (int it = 0; it < 4; it++) {
            int i = tid + it * 256;          // [0,1024) float4s
            int r = i >> 4;
            int c = (i & 15) << 2;
            float4 v = *(const float4*)(Q + base + (size_t)(q0 + r) * DH + c);
            float* d = sQ + r * PAD + c;
            d[0] = v.x * scale; d[1] = v.y * scale;
            d[2] = v.z * scale; d[3] = v.w * scale;
        }
    }
    if (tid < BM) { sM[tid] = -1e30f; sL[tid] = 0.0f; }

    float acc[4][4];
    #pragma unroll
    for (int i = 0; i < 4; i++)
        #pragma unroll
        for (int c = 0; c < 4; c++) acc[i][c] = 0.0f;

    __syncthreads();

    for (int kt = 0; kt < S_LEN; kt += BN) {
        // ---- load K transposed (bank-conflict-free STS: key index is
        //      consecutive across lanes) and V natural (coalesced) ----
        #pragma unroll
        for (int it = 0; it < 4; it++) {
            int i  = tid + it * 256;         // [0,1024)
            // K: r = key (lane-consecutive), kq*4 = dh quad
            int rk = i & 63;
            int c4 = (i >> 6) << 2;
            float4 kv = *(const float4*)(K + base + (size_t)(kt + rk) * DH + c4);
            sKT[(c4 + 0) * PAD + rk] = kv.x;
            sKT[(c4 + 1) * PAD + rk] = kv.y;
            sKT[(c4 + 2) * PAD + rk] = kv.z;
            sKT[(c4 + 3) * PAD + rk] = kv.w;
            // V: coalesced natural layout
            int rv = i >> 4;
            int cv = (i & 15) << 2;
            float4 vv = *(const float4*)(V + base + (size_t)(kt + rv) * DH + cv);
            *(float4*)(sV + rv * PAD + cv) = vv;
        }
        __syncthreads();

        // ---- S = Q @ K^T (4x4 micro-tile, k-quad unrolled) ----
        float sa[4][4];
        #pragma unroll
        for (int i = 0; i < 4; i++)
            #pragma unroll
            for (int c = 0; c < 4; c++) sa[i][c] = 0.0f;

        #pragma unroll
        for (int k = 0; k < DH; k += 4) {
            float4 A[4], B[4];
            #pragma unroll
            for (int i = 0; i < 4; i++)
                A[i] = *(const float4*)(sQ + (4 * ty + i) * PAD + k);
            #pragma unroll
            for (int j = 0; j < 4; j++)
                B[j] = *(const float4*)(sKT + (k + j) * PAD + 4 * tx);
            const float* af = (const float*)A;
            const float* bf = (const float*)B;
            #pragma unroll
            for (int i = 0; i < 4; i++)
                #pragma unroll
                for (int kk = 0; kk < 4; kk++)
                    #pragma unroll
                    for (int c = 0; c < 4; c++)
                        sa[i][c] += af[i * 4 + kk] * bf[kk * 4 + c];
        }

        // ---- add mask, park scores in sP ----
        #pragma unroll
        for (int i = 0; i < 4; i++) {
            float4 mk = *(const float4*)(mask + (size_t)(q0 + 4 * ty + i) * S_LEN + kt + 4 * tx);
            float* d = sP + (4 * ty + i) * PAD + 4 * tx;
            d[0] = sa[i][0] + mk.x; d[1] = sa[i][1] + mk.y;
            d[2] = sa[i][2] + mk.z; d[3] = sa[i][3] + mk.w;
        }
        __syncthreads();

        // ---- online softmax: 4 threads per row, 16 cols each ----
        const int row  = tid >> 2;
        const int part = tid & 3;
        {
            const float* pr = sP + row * PAD + part * 16;
            float pm = -1e30f;
            #pragma unroll
            for (int c = 0; c < 16; c++) pm = fmaxf(pm, pr[c]);
            sRed[row * 4 + part] = pm;
        }
        __syncthreads();
        if (part == 0) {
            float mo = sM[row];
            float mn = fmaxf(fmaxf(sRed[row * 4 + 0], sRed[row * 4 + 1]),
                             fmaxf(sRed[row * 4 + 2], sRed[row * 4 + 3]));
            mn = fmaxf(mo, mn);
            sM[row] = mn;
            sC[row] = __expf(mo - mn);
        }
        __syncthreads();
        {
            float mn = sM[row];
            float* prw = sP + row * PAD + part * 16;
            float ps = 0.0f;
            #pragma unroll
            for (int c = 0; c < 16; c++) {
                float p = __expf(prw[c] - mn);
                prw[c] = p;
                ps += p;
            }
            sRed[row * 4 + part] = ps;
        }
        __syncthreads();
        if (part == 0) {
            sL[row] = sL[row] * sC[row] +
                      (sRed[row * 4 + 0] + sRed[row * 4 + 1] +
                       sRed[row * 4 + 2] + sRed[row * 4 + 3]);
        }

        // ---- rescale O and accumulate O += P @ V ----
        {
            float cr[4];
            #pragma unroll
            for (int i = 0; i < 4; i++) cr[i] = sC[4 * ty + i];
            #pragma unroll
            for (int i = 0; i < 4; i++)
                #pragma unroll
                for (int c = 0; c < 4; c++) acc[i][c] *= cr[i];
        }
        #pragma unroll
        for (int j = 0; j < BN; j += 4) {
            float4 A[4], B[4];
            #pragma unroll
            for (int i = 0; i < 4; i++)
                A[i] = *(const float4*)(sP + (4 * ty + i) * PAD + j);
            #pragma unroll
            for (int jj = 0; jj < 4; jj++)
                B[jj] = *(const float4*)(sV + (j + jj) * PAD + 4 * tx);
            const float* af = (const float*)A;
            const float* bf = (const float*)B;
            #pragma unroll
            for (int i = 0; i < 4; i++)
                #pragma unroll
                for (int kk = 0; kk < 4; kk++)
                    #pragma unroll
                    for (int c = 0; c < 4; c++)
                        acc[i][c] += af[i * 4 + kk] * bf[kk * 4 + c];
        }
        __syncthreads();   // protect sKT/sV/sP/sRed for next tile
    }

    // ---- epilogue: divide by denom, store to g_x ----
    #pragma unroll
    for (int i = 0; i < 4; i++) {
        int r = 4 * ty + i;
        float inv = 1.0f / sL[r];
        float4 o;
        o.x = acc[i][0] * inv; o.y = acc[i][1] * inv;
        o.z = acc[i][2] * inv; o.w = acc[i][3] * inv;
        *(float4*)(g_x + base + (size_t)(q0 + r) * DH + 4 * tx) = o;
    }
}

// ---------------------------------------------------------------------------
// Projection: out[M=4096, N=1024] = x @ W^T + b. Grid (N/64, M/64), 256 thr.
// ---------------------------------------------------------------------------
__global__ __launch_bounds__(256, 2)
void proj_kernel(const float* __restrict__ W, const float* __restrict__ bias,
                 float* __restrict__ out)
{
    __shared__ float sX [BM * PAD];   // [m][k]
    __shared__ float sWT[BN * PAD];   // [k][n] (W transposed)

    const int tid = threadIdx.x;
    const int tx  = tid & 15;
    const int ty  = tid >> 4;
    const int n0  = blockIdx.x * 64;
    const int m0  = blockIdx.y * 64;

    float acc[4][4];
    #pragma unroll
    for (int i = 0; i < 4; i++)
        #pragma unroll
        for (int c = 0; c < 4; c++) acc[i][c] = 0.0f;

    for (int kt = 0; kt < DMODEL; kt += 64) {
        #pragma unroll
        for (int it = 0; it < 4; it++) {
            int i = tid + it * 256;          // [0,1024) float4s
            // X tile: coalesced
            int r = i >> 4;
            int c = (i & 15) << 2;
            *(float4*)(sX + r * PAD + c) =
                *(const float4*)(g_x + (size_t)(m0 + r) * DMODEL + kt + c);
            // W tile transposed: n lane-consecutive -> conflict-free STS
            int n  = i & 63;
            int k4 = (i >> 6) << 2;
            float4 wv = *(const float4*)(W + (size_t)(n0 + n) * DMODEL + kt + k4);
            sWT[(k4 + 0) * PAD + n] = wv.x;
            sWT[(k4 + 1) * PAD + n] = wv.y;
            sWT[(k4 + 2) * PAD + n] = wv.z;
            sWT[(k4 + 3) * PAD + n] = wv.w;
        }
        __syncthreads();

        #pragma unroll
        for (int k = 0; k < 64; k += 4) {
            float4 A[4], B[4];
            #pragma unroll
            for (int i = 0; i < 4; i++)
                A[i] = *(const float4*)(sX + (4 * ty + i) * PAD + k);
            #pragma unroll
            for (int j = 0; j < 4; j++)
                B[j] = *(const float4*)(sWT + (k + j) * PAD + 4 * tx);
            const float* af = (const float*)A;
            const float* bf = (const float*)B;
            #pragma unroll
            for (int i = 0; i < 4; i++)
                #pragma unroll
                for (int kk = 0; kk < 4; kk++)
                    #pragma unroll
                    for (int c = 0; c < 4; c++)
                        acc[i][c] += af[i * 4 + kk] * bf[kk * 4 + c];
        }
        __syncthreads();
    }

    float4 bv = *(const float4*)(bias + n0 + 4 * tx);
    #pragma unroll
    for (int i = 0; i < 4; i++) {
        int m = m0 + 4 * ty + i;
        float4 o;
        o.x = acc[i][0] + bv.x; o.y = acc[i][1] + bv.y;
        o.z = acc[i][2] + bv.z; o.w = acc[i][3] + bv.w;
        *(float4*)(out + (size_t)m * DMODEL + n0 + 4 * tx) = o;
    }
}

// ---------------------------------------------------------------------------
extern "C" void kernel_launch(void* const* d_in, const int* in_sizes, int n_in,
                              void* d_out, int out_size)
{
    const float* Q    = (const float*)d_in[0];
    const float* K    = (const float*)d_in[1];
    const float* V    = (const float*)d_in[2];
    const float* mask = (const float*)d_in[3];
    const float* W    = (const float*)d_in[4];
    const float* bias = (const float*)d_in[5];
    float* out        = (float*)d_out;

    const size_t smem_bytes = (size_t)(4 * BM * PAD + 7 * BM) * sizeof(float); // 71424 B
    cudaFuncSetAttribute(attn_kernel, cudaFuncAttributeMaxDynamicSharedMemorySize,
                         (int)smem_bytes);

    dim3 agrid(S_LEN / BM, BATCH * HEADS);   // (32, 32)
    attn_kernel<<<agrid, 256, smem_bytes>>>(Q, K, V, mask);

    dim3 pgrid(DMODEL / 64, BATCH * S_LEN / 64);  // (16, 64)
    proj_kernel<<<pgrid, 256>>>(W, bias, out);
}

// round 7
// speedup vs baseline: 1.7738x; 1.7738x over previous
#include <cuda_runtime.h>

#define S_LEN   2048
#define DH      64
#define HEADS   16
#define BATCH   2
#define DMODEL  1024

#define BM      128     // query rows / output rows per CTA
#define BN      64      // key tile / output cols per CTA
#define PADR    68      // padded float row stride (16B aligned)

// Intermediate attention output x = vals.reshape(B,S,DMODEL)  (16 MB)
__device__ float g_x[BATCH * S_LEN * DMODEL];

// ---------------------------------------------------------------------------
// Flash attention: grid (S/BM=16, B*H=32), 256 threads, 2 CTAs/SM.
// Q/K/V slabs are contiguous [S,64] at base=(b*H+h)*S*DH (direct reshape).
// 8x4 register micro-tile: rows 8*ty+i (ty=tid>>4), cols 4*tx (tx=tid&15).
// ---------------------------------------------------------------------------
__global__ __launch_bounds__(256, 2)
void attn_kernel(const float* __restrict__ Q, const float* __restrict__ K,
                 const float* __restrict__ V, const float* __restrict__ mask)
{
    extern __shared__ float sm[];
    float* sQ  = sm;                 // [BM][PADR]  pre-scaled Q
    float* sKT = sQ  + BM * PADR;    // [DH][PADR]  K transposed (k-major)
    float* sV  = sKT + DH * PADR;    // [BN][PADR]  V natural
    float* sP  = sV  + BN * PADR;    // [BM][PADR]  scores -> probs
    float* sM  = sP  + BM * PADR;    // [BM] running max
    float* sL  = sM  + BM;           // [BM] running denom
    float* sC  = sL  + BM;           // [BM] correction

    const int tid = threadIdx.x;
    const int tx  = tid & 15;
    const int ty  = tid >> 4;
    const int q0  = blockIdx.x * BM;
    const size_t base = (size_t)blockIdx.y * (S_LEN * DH);

    // ---- load Q tile (128x64), scaled by 1/sqrt(64) ----
    {
        const float scale = 0.125f;
        #pragma unroll
        for (int it = 0; it < 8; it++) {
            int i = tid + it * 256;          // [0,2048) float4s
            int r = i >> 4;
            int c = (i & 15) << 2;
            float4 v = *(const float4*)(Q + base + (size_t)(q0 + r) * DH + c);
            float* d = sQ + r * PADR + c;
            d[0] = v.x * scale; d[1] = v.y * scale;
            d[2] = v.z * scale; d[3] = v.w * scale;
        }
    }
    if (tid < BM) { sM[tid] = -1e30f; sL[tid] = 0.0f; }

    float acc[8][4];                 // O accumulator (rows 8ty+i, cols 4tx+c)
    #pragma unroll
    for (int i = 0; i < 8; i++)
        #pragma unroll
        for (int c = 0; c < 4; c++) acc[i][c] = 0.0f;

    __syncthreads();

    for (int kt = 0; kt < S_LEN; kt += BN) {
        // ---- load K transposed (conflict-free scatter STS) + V natural ----
        #pragma unroll
        for (int it = 0; it < 4; it++) {
            int i  = tid + it * 256;         // [0,1024) float4s
            int rk = i & 63;                 // key (lane-consecutive)
            int c4 = (i >> 6) << 2;          // dh quad
            float4 kv = *(const float4*)(K + base + (size_t)(kt + rk) * DH + c4);
            sKT[(c4 + 0) * PADR + rk] = kv.x;
            sKT[(c4 + 1) * PADR + rk] = kv.y;
            sKT[(c4 + 2) * PADR + rk] = kv.z;
            sKT[(c4 + 3) * PADR + rk] = kv.w;
            int rv = i >> 4;                 // key row 0..63
            int cv = (i & 15) << 2;
            float4 vv = *(const float4*)(V + base + (size_t)(kt + rv) * DH + cv);
            *(float4*)(sV + rv * PADR + cv) = vv;
        }
        __syncthreads();

        // ---- S = Q @ K^T  (8x4 micro-tile) ----
        float sa[8][4];
        #pragma unroll
        for (int i = 0; i < 8; i++)
            #pragma unroll
            for (int c = 0; c < 4; c++) sa[i][c] = 0.0f;

        #pragma unroll
        for (int k = 0; k < DH; k += 4) {
            float4 A[8];
            #pragma unroll
            for (int i = 0; i < 8; i++)
                A[i] = *(const float4*)(sQ + (8 * ty + i) * PADR + k);
            #pragma unroll
            for (int kk = 0; kk < 4; kk++) {
                float4 Bv = *(const float4*)(sKT + (k + kk) * PADR + 4 * tx);
                const float* bf = (const float*)&Bv;
                #pragma unroll
                for (int i = 0; i < 8; i++) {
                    float a = ((const float*)&A[i])[kk];
                    #pragma unroll
                    for (int c = 0; c < 4; c++)
                        sa[i][c] += a * bf[c];
                }
            }
        }

        // ---- add mask, park scores in sP ----
        #pragma unroll
        for (int i = 0; i < 8; i++) {
            int r = 8 * ty + i;
            float4 mk = *(const float4*)(mask + (size_t)(q0 + r) * S_LEN + kt + 4 * tx);
            float* d = sP + r * PADR + 4 * tx;
            d[0] = sa[i][0] + mk.x; d[1] = sa[i][1] + mk.y;
            d[2] = sa[i][2] + mk.z; d[3] = sa[i][3] + mk.w;
        }
        __syncthreads();

        // ---- online softmax: 2 adjacent lanes per row, shfl combine ----
        {
            const int row  = tid >> 1;
            const int part = tid & 1;
            float* pr = sP + row * PADR + part * 32;

            float pm = -1e30f;
            #pragma unroll
            for (int v4 = 0; v4 < 8; v4++) {
                float4 v = *(const float4*)(pr + 4 * v4);
                pm = fmaxf(pm, fmaxf(fmaxf(v.x, v.y), fmaxf(v.z, v.w)));
            }
            pm = fmaxf(pm, __shfl_xor_sync(0xffffffffu, pm, 1));
            float mo = sM[row];
            float mn = fmaxf(mo, pm);
            float corr = __expf(mo - mn);
            if (part == 0) { sM[row] = mn; sC[row] = corr; }

            float ps = 0.0f;
            #pragma unroll
            for (int v4 = 0; v4 < 8; v4++) {
                float4 v = *(const float4*)(pr + 4 * v4);
                v.x = __expf(v.x - mn); v.y = __expf(v.y - mn);
                v.z = __expf(v.z - mn); v.w = __expf(v.w - mn);
                *(float4*)(pr + 4 * v4) = v;
                ps += v.x + v.y + v.z + v.w;
            }
            ps += __shfl_xor_sync(0xffffffffu, ps, 1);
            if (part == 0) sL[row] = sL[row] * corr + ps;
        }
        __syncthreads();

        // ---- rescale O, accumulate O += P @ V ----
        #pragma unroll
        for (int i = 0; i < 8; i++) {
            float cr = sC[8 * ty + i];
            #pragma unroll
            for (int c = 0; c < 4; c++) acc[i][c] *= cr;
        }
        #pragma unroll
        for (int k = 0; k < BN; k += 4) {
            float4 A[8];
            #pragma unroll
            for (int i = 0; i < 8; i++)
                A[i] = *(const float4*)(sP + (8 * ty + i) * PADR + k);
            #pragma unroll
            for (int kk = 0; kk < 4; kk++) {
                float4 Bv = *(const float4*)(sV + (k + kk) * PADR + 4 * tx);
                const float* bf = (const float*)&Bv;
                #pragma unroll
                for (int i = 0; i < 8; i++) {
                    float a = ((const float*)&A[i])[kk];
                    #pragma unroll
                    for (int c = 0; c < 4; c++)
                        acc[i][c] += a * bf[c];
                }
            }
        }
        __syncthreads();   // protect sKT/sV/sP/sC/sM before next tile
    }

    // ---- epilogue: divide by denom, store to g_x ----
    #pragma unroll
    for (int i = 0; i < 8; i++) {
        int r = 8 * ty + i;
        float inv = 1.0f / sL[r];
        float4 o;
        o.x = acc[i][0] * inv; o.y = acc[i][1] * inv;
        o.z = acc[i][2] * inv; o.w = acc[i][3] * inv;
        *(float4*)(g_x + base + (size_t)(q0 + r) * DH + 4 * tx) = o;
    }
}

// ---------------------------------------------------------------------------
// Projection: out[4096,1024] = x @ W^T + b. Grid (N/64=16, M/128=32), 256 thr.
// Same 8x4 micro-kernel, k-tile 64, 2 CTAs/SM.
// ---------------------------------------------------------------------------
__global__ __launch_bounds__(256, 2)
void proj_kernel(const float* __restrict__ W, const float* __restrict__ bias,
                 float* __restrict__ out)
{
    extern __shared__ float sm[];
    float* sX  = sm;                 // [BM][PADR]
    float* sWT = sX + BM * PADR;     // [64][PADR]  W transposed (k-major)

    const int tid = threadIdx.x;
    const int tx  = tid & 15;
    const int ty  = tid >> 4;
    const int n0  = blockIdx.x * BN;
    const int m0  = blockIdx.y * BM;

    float acc[8][4];
    #pragma unroll
    for (int i = 0; i < 8; i++)
        #pragma unroll
        for (int c = 0; c < 4; c++) acc[i][c] = 0.0f;

    for (int kt = 0; kt < DMODEL; kt += 64) {
        // X tile (128x64) coalesced
        #pragma unroll
        for (int it = 0; it < 8; it++) {
            int i = tid + it * 256;          // [0,2048) float4s
            int r = i >> 4;
            int c = (i & 15) << 2;
            *(float4*)(sX + r * PADR + c) =
                *(const float4*)(g_x + (size_t)(m0 + r) * DMODEL + kt + c);
        }
        // W tile (64n x 64k) transposed scatter
        #pragma unroll
        for (int it = 0; it < 4; it++) {
            int i  = tid + it * 256;         // [0,1024)
            int n  = i & 63;
            int k4 = (i >> 6) << 2;
            float4 wv = *(const float4*)(W + (size_t)(n0 + n) * DMODEL + kt + k4);
            sWT[(k4 + 0) * PADR + n] = wv.x;
            sWT[(k4 + 1) * PADR + n] = wv.y;
            sWT[(k4 + 2) * PADR + n] = wv.z;
            sWT[(k4 + 3) * PADR + n] = wv.w;
        }
        __syncthreads();

        #pragma unroll
        for (int k = 0; k < 64; k += 4) {
            float4 A[8];
            #pragma unroll
            for (int i = 0; i < 8; i++)
                A[i] = *(const float4*)(sX + (8 * ty + i) * PADR + k);
            #pragma unroll
            for (int kk = 0; kk < 4; kk++) {
                float4 Bv = *(const float4*)(sWT + (k + kk) * PADR + 4 * tx);
                const float* bf = (const float*)&Bv;
                #pragma unroll
                for (int i = 0; i < 8; i++) {
                    float a = ((const float*)&A[i])[kk];
                    #pragma unroll
                    for (int c = 0; c < 4; c++)
                        acc[i][c] += a * bf[c];
                }
            }
        }
        __syncthreads();
    }

    float4 bv = *(const float4*)(bias + n0 + 4 * tx);
    #pragma unroll
    for (int i = 0; i < 8; i++) {
        int m = m0 + 8 * ty + i;
        float4 o;
        o.x = acc[i][0] + bv.x; o.y = acc[i][1] + bv.y;
        o.z = acc[i][2] + bv.z; o.w = acc[i][3] + bv.w;
        *(float4*)(out + (size_t)m * DMODEL + n0 + 4 * tx) = o;
    }
}

// ---------------------------------------------------------------------------
extern "C" void kernel_launch(void* const* d_in, const int* in_sizes, int n_in,
                              void* d_out, int out_size)
{
    const float* Q    = (const float*)d_in[0];
    const float* K    = (const float*)d_in[1];
    const float* V    = (const float*)d_in[2];
    const float* mask = (const float*)d_in[3];
    const float* W    = (const float*)d_in[4];
    const float* bias = (const float*)d_in[5];
    float* out        = (float*)d_out;

    // attn smem: (128+64+64+128)*68 + 3*128 floats = 26496+384 = 26880 fl
    const size_t attn_smem = (size_t)((BM + DH + BN + BM) * PADR + 3 * BM) * sizeof(float);
    cudaFuncSetAttribute(attn_kernel, cudaFuncAttributeMaxDynamicSharedMemorySize,
                         (int)attn_smem);
    // proj smem: (128+64)*68 floats = 13056 fl = 52224 B
    const size_t proj_smem = (size_t)((BM + 64) * PADR) * sizeof(float);
    cudaFuncSetAttribute(proj_kernel, cudaFuncAttributeMaxDynamicSharedMemorySize,
                         (int)proj_smem);

    dim3 agrid(S_LEN / BM, BATCH * HEADS);        // (16, 32)
    attn_kernel<<<agrid, 256, attn_smem>>>(Q, K, V, mask);

    dim3 pgrid(DMODEL / BN, BATCH * S_LEN / BM);  // (16, 32)
    proj_kernel<<<pgrid, 256, proj_smem>>>(W, bias, out);
}

// round 8
// speedup vs baseline: 2.9307x; 1.6522x over previous
#include <cuda_runtime.h>
#include <cuda_bf16.h>
#include <stdint.h>

#define S_LEN   2048
#define DH      64
#define HEADS   16
#define BATCH   2
#define DMODEL  1024

#define BM      128     // query rows / output rows per CTA
#define BN      64      // key tile / output cols per CTA
#define PADH    72      // bf16 row stride (144B: conflict-free ldmatrix)

// Intermediate attention output x = vals.reshape(B,S,DMODEL) (16 MB)
__device__ float g_x[BATCH * S_LEN * DMODEL];

// ---------------------------------------------------------------------------
// PTX helpers
// ---------------------------------------------------------------------------
__device__ __forceinline__ uint32_t cvta_s(const void* p) {
    return (uint32_t)__cvta_generic_to_shared(p);
}
__device__ __forceinline__ void ldsm_x4(uint32_t* r, uint32_t a) {
    asm volatile("ldmatrix.sync.aligned.m8n8.x4.shared.b16 {%0,%1,%2,%3}, [%4];"
        : "=r"(r[0]), "=r"(r[1]), "=r"(r[2]), "=r"(r[3]) : "r"(a));
}
__device__ __forceinline__ void ldsm_x2(uint32_t* r, uint32_t a) {
    asm volatile("ldmatrix.sync.aligned.m8n8.x2.shared.b16 {%0,%1}, [%2];"
        : "=r"(r[0]), "=r"(r[1]) : "r"(a));
}
__device__ __forceinline__ void ldsm_x2t(uint32_t* r, uint32_t a) {
    asm volatile("ldmatrix.sync.aligned.m8n8.x2.trans.shared.b16 {%0,%1}, [%2];"
        : "=r"(r[0]), "=r"(r[1]) : "r"(a));
}
__device__ __forceinline__ void mma_bf(float* c, const uint32_t* a, const uint32_t* b) {
    asm volatile("mma.sync.aligned.m16n8k16.row.col.f32.bf16.bf16.f32 "
        "{%0,%1,%2,%3}, {%4,%5,%6,%7}, {%8,%9}, {%0,%1,%2,%3};"
        : "+f"(c[0]), "+f"(c[1]), "+f"(c[2]), "+f"(c[3])
        : "r"(a[0]), "r"(a[1]), "r"(a[2]), "r"(a[3]), "r"(b[0]), "r"(b[1]));
}
__device__ __forceinline__ uint32_t packbf(float x, float y) {
    __nv_bfloat162 h = __floats2bfloat162_rn(x, y);
    return *(uint32_t*)&h;
}
// hi = bf16(x); lo = bf16(x - hi): 3-product split -> ~2^-16 rel error
__device__ __forceinline__ void split_pack(float x, float y, uint32_t& hi, uint32_t& lo) {
    float hx = __bfloat162float(__float2bfloat16(x));
    float hy = __bfloat162float(__float2bfloat16(y));
    hi = packbf(hx, hy);
    lo = packbf(x - hx, y - hy);
}
__device__ __forceinline__ void split4_store(__nv_bfloat16* hi, __nv_bfloat16* lo, float4 v) {
    float hx = __bfloat162float(__float2bfloat16(v.x));
    float hy = __bfloat162float(__float2bfloat16(v.y));
    float hz = __bfloat162float(__float2bfloat16(v.z));
    float hw = __bfloat162float(__float2bfloat16(v.w));
    uint2 h2; h2.x = packbf(hx, hy);        h2.y = packbf(hz, hw);
    uint2 l2; l2.x = packbf(v.x-hx, v.y-hy); l2.y = packbf(v.z-hz, v.w-hw);
    *(uint2*)hi = h2;
    *(uint2*)lo = l2;
}

// ---------------------------------------------------------------------------
// Flash attention, mma.sync bf16-split. grid (16, 32), 256 thr, 2 CTA/SM.
// Warp w owns query rows [w*16, w*16+16). Thread quad: g=lane>>2, qd=lane&3.
// ---------------------------------------------------------------------------
__global__ __launch_bounds__(256, 2)
void attn_kernel(const float* __restrict__ Q, const float* __restrict__ K,
                 const float* __restrict__ V, const float* __restrict__ mask)
{
    extern __shared__ __nv_bfloat16 sb[];
    __nv_bfloat16* sQh = sb;
    __nv_bfloat16* sQl = sQh + BM * PADH;
    __nv_bfloat16* sKh = sQl + BM * PADH;
    __nv_bfloat16* sKl = sKh + BN * PADH;
    __nv_bfloat16* sVh = sKl + BN * PADH;
    __nv_bfloat16* sVl = sVh + BN * PADH;

    const int tid  = threadIdx.x;
    const int warp = tid >> 5;
    const int lane = tid & 31;
    const int g    = lane >> 2;
    const int qd   = lane & 3;
    const int l16  = lane & 15;
    const int mrow = warp * 16;
    const int q0   = blockIdx.x * BM;
    const size_t base = (size_t)blockIdx.y * (S_LEN * DH);

    // ---- convert Q tile (scaled by 1/8) into hi/lo bf16 ----
    #pragma unroll
    for (int it = 0; it < 8; it++) {
        int i = tid + it * 256;              // [0,2048) float4s
        int r = i >> 4, c = (i & 15) << 2;
        float4 v = *(const float4*)(Q + base + (size_t)(q0 + r) * DH + c);
        v.x *= 0.125f; v.y *= 0.125f; v.z *= 0.125f; v.w *= 0.125f;
        split4_store(sQh + r * PADH + c, sQl + r * PADH + c, v);
    }

    const uint32_t qh32 = cvta_s(sQh), ql32 = cvta_s(sQl);
    const uint32_t kh32 = cvta_s(sKh), kl32 = cvta_s(sKl);
    const uint32_t vh32 = cvta_s(sVh), vl32 = cvta_s(sVl);

    float o[8][4];
    #pragma unroll
    for (int n = 0; n < 8; n++)
        #pragma unroll
        for (int c = 0; c < 4; c++) o[n][c] = 0.0f;
    float m0r = -1e30f, m1r = -1e30f, l0r = 0.0f, l1r = 0.0f;

    const float* mk0 = mask + (size_t)(q0 + mrow + g) * S_LEN;
    const float* mk1 = mk0 + 8 * S_LEN;

    for (int kt = 0; kt < S_LEN; kt += BN) {
        // ---- convert K,V tiles to hi/lo bf16 ----
        #pragma unroll
        for (int it = 0; it < 4; it++) {
            int i = tid + it * 256;          // [0,1024) float4s
            int r = i >> 4, c = (i & 15) << 2;
            float4 kv = *(const float4*)(K + base + (size_t)(kt + r) * DH + c);
            split4_store(sKh + r * PADH + c, sKl + r * PADH + c, kv);
            float4 vv = *(const float4*)(V + base + (size_t)(kt + r) * DH + c);
            split4_store(sVh + r * PADH + c, sVl + r * PADH + c, vv);
        }
        __syncthreads();

        // ---- S = Q @ K^T (3-product bf16 split) ----
        float s[8][4];
        #pragma unroll
        for (int n = 0; n < 8; n++)
            #pragma unroll
            for (int c = 0; c < 4; c++) s[n][c] = 0.0f;

        #pragma unroll
        for (int k = 0; k < 4; k++) {
            uint32_t ah[4], al[4];
            uint32_t ao = (uint32_t)(((mrow + l16) * PADH + k * 16 + (lane >> 4) * 8) * 2);
            ldsm_x4(ah, qh32 + ao);
            ldsm_x4(al, ql32 + ao);
            #pragma unroll
            for (int n = 0; n < 8; n++) {
                uint32_t bh[2], bl[2];
                uint32_t bo = (uint32_t)(((n * 8 + (l16 & 7)) * PADH + k * 16 + (l16 >> 3) * 8) * 2);
                ldsm_x2(bh, kh32 + bo);
                ldsm_x2(bl, kl32 + bo);
                mma_bf(s[n], ah, bh);
                mma_bf(s[n], ah, bl);
                mma_bf(s[n], al, bh);
            }
        }

        // ---- add mask ----
        #pragma unroll
        for (int n = 0; n < 8; n++) {
            float2 a = *(const float2*)(mk0 + kt + n * 8 + qd * 2);
            float2 b = *(const float2*)(mk1 + kt + n * 8 + qd * 2);
            s[n][0] += a.x; s[n][1] += a.y; s[n][2] += b.x; s[n][3] += b.y;
        }

        // ---- online softmax (stats per thread-quad via shfl) ----
        float mx0 = -1e30f, mx1 = -1e30f;
        #pragma unroll
        for (int n = 0; n < 8; n++) {
            mx0 = fmaxf(mx0, fmaxf(s[n][0], s[n][1]));
            mx1 = fmaxf(mx1, fmaxf(s[n][2], s[n][3]));
        }
        mx0 = fmaxf(mx0, __shfl_xor_sync(0xffffffffu, mx0, 1));
        mx0 = fmaxf(mx0, __shfl_xor_sync(0xffffffffu, mx0, 2));
        mx1 = fmaxf(mx1, __shfl_xor_sync(0xffffffffu, mx1, 1));
        mx1 = fmaxf(mx1, __shfl_xor_sync(0xffffffffu, mx1, 2));
        float mn0 = fmaxf(m0r, mx0), mn1 = fmaxf(m1r, mx1);
        float c0 = __expf(m0r - mn0), c1 = __expf(m1r - mn1);
        m0r = mn0; m1r = mn1;

        float s0 = 0.0f, s1 = 0.0f;
        #pragma unroll
        for (int n = 0; n < 8; n++) {
            s[n][0] = __expf(s[n][0] - mn0); s[n][1] = __expf(s[n][1] - mn0);
            s[n][2] = __expf(s[n][2] - mn1); s[n][3] = __expf(s[n][3] - mn1);
            s0 += s[n][0] + s[n][1];
            s1 += s[n][2] + s[n][3];
        }
        s0 += __shfl_xor_sync(0xffffffffu, s0, 1);
        s0 += __shfl_xor_sync(0xffffffffu, s0, 2);
        s1 += __shfl_xor_sync(0xffffffffu, s1, 1);
        s1 += __shfl_xor_sync(0xffffffffu, s1, 2);
        l0r = l0r * c0 + s0;
        l1r = l1r * c1 + s1;

        #pragma unroll
        for (int n = 0; n < 8; n++) {
            o[n][0] *= c0; o[n][1] *= c0; o[n][2] *= c1; o[n][3] *= c1;
        }

        // ---- O += P @ V (P frags built in registers from S frags) ----
        #pragma unroll
        for (int k = 0; k < 4; k++) {
            uint32_t ph[4], pl[4];
            split_pack(s[2*k  ][0], s[2*k  ][1], ph[0], pl[0]);
            split_pack(s[2*k  ][2], s[2*k  ][3], ph[1], pl[1]);
            split_pack(s[2*k+1][0], s[2*k+1][1], ph[2], pl[2]);
            split_pack(s[2*k+1][2], s[2*k+1][3], ph[3], pl[3]);
            #pragma unroll
            for (int n = 0; n < 8; n++) {
                uint32_t bh[2], bl[2];
                uint32_t bo = (uint32_t)(((k * 16 + l16) * PADH + n * 8) * 2);
                ldsm_x2t(bh, vh32 + bo);
                ldsm_x2t(bl, vl32 + bo);
                mma_bf(o[n], ph, bh);
                mma_bf(o[n], ph, bl);
                mma_bf(o[n], pl, bh);
            }
        }
        __syncthreads();   // protect K/V tiles before next iteration
    }

    // ---- epilogue: O /= l, store to g_x ----
    float i0 = 1.0f / l0r, i1 = 1.0f / l1r;
    float* od0 = g_x + base + (size_t)(q0 + mrow + g) * DH;
    float* od1 = od0 + 8 * DH;
    #pragma unroll
    for (int n = 0; n < 8; n++) {
        float2 a; a.x = o[n][0] * i0; a.y = o[n][1] * i0;
        float2 b; b.x = o[n][2] * i1; b.y = o[n][3] * i1;
        *(float2*)(od0 + n * 8 + qd * 2) = a;
        *(float2*)(od1 + n * 8 + qd * 2) = b;
    }
}

// ---------------------------------------------------------------------------
// Projection: out[4096,1024] = x @ W^T + b, same mma structure.
// grid (DMODEL/64=16, 4096/128=32), 256 threads.
// ---------------------------------------------------------------------------
__global__ __launch_bounds__(256, 2)
void proj_kernel(const float* __restrict__ W, const float* __restrict__ bias,
                 float* __restrict__ out)
{
    extern __shared__ __nv_bfloat16 sb[];
    __nv_bfloat16* sXh = sb;
    __nv_bfloat16* sXl = sXh + BM * PADH;
    __nv_bfloat16* sWh = sXl + BM * PADH;
    __nv_bfloat16* sWl = sWh + BN * PADH;

    const int tid  = threadIdx.x;
    const int warp = tid >> 5;
    const int lane = tid & 31;
    const int g    = lane >> 2;
    const int qd   = lane & 3;
    const int l16  = lane & 15;
    const int mrow = warp * 16;
    const int n0   = blockIdx.x * BN;
    const int m0   = blockIdx.y * BM;

    const uint32_t xh32 = cvta_s(sXh), xl32 = cvta_s(sXl);
    const uint32_t wh32 = cvta_s(sWh), wl32 = cvta_s(sWl);

    float o[8][4];
    #pragma unroll
    for (int n = 0; n < 8; n++)
        #pragma unroll
        for (int c = 0; c < 4; c++) o[n][c] = 0.0f;

    for (int kt = 0; kt < DMODEL; kt += 64) {
        #pragma unroll
        for (int it = 0; it < 8; it++) {
            int i = tid + it * 256;          // [0,2048) float4s
            int r = i >> 4, c = (i & 15) << 2;
            float4 v = *(const float4*)(g_x + (size_t)(m0 + r) * DMODEL + kt + c);
            split4_store(sXh + r * PADH + c, sXl + r * PADH + c, v);
        }
        #pragma unroll
        for (int it = 0; it < 4; it++) {
            int i = tid + it * 256;          // [0,1024) float4s
            int r = i >> 4, c = (i & 15) << 2;
            float4 v = *(const float4*)(W + (size_t)(n0 + r) * DMODEL + kt + c);
            split4_store(sWh + r * PADH + c, sWl + r * PADH + c, v);
        }
        __syncthreads();

        #pragma unroll
        for (int k = 0; k < 4; k++) {
            uint32_t ah[4], al[4];
            uint32_t ao = (uint32_t)(((mrow + l16) * PADH + k * 16 + (lane >> 4) * 8) * 2);
            ldsm_x4(ah, xh32 + ao);
            ldsm_x4(al, xl32 + ao);
            #pragma unroll
            for (int n = 0; n < 8; n++) {
                uint32_t bh[2], bl[2];
                uint32_t bo = (uint32_t)(((n * 8 + (l16 & 7)) * PADH + k * 16 + (l16 >> 3) * 8) * 2);
                ldsm_x2(bh, wh32 + bo);
                ldsm_x2(bl, wl32 + bo);
                mma_bf(o[n], ah, bh);
                mma_bf(o[n], ah, bl);
                mma_bf(o[n], al, bh);
            }
        }
        __syncthreads();
    }

    float* od0 = out + (size_t)(m0 + mrow + g) * DMODEL + n0;
    float* od1 = od0 + 8 * DMODEL;
    #pragma unroll
    for (int n = 0; n < 8; n++) {
        float2 bv = *(const float2*)(bias + n0 + n * 8 + qd * 2);
        float2 a; a.x = o[n][0] + bv.x; a.y = o[n][1] + bv.y;
        float2 b; b.x = o[n][2] + bv.x; b.y = o[n][3] + bv.y;
        *(float2*)(od0 + n * 8 + qd * 2) = a;
        *(float2*)(od1 + n * 8 + qd * 2) = b;
    }
}

// ---------------------------------------------------------------------------
extern "C" void kernel_launch(void* const* d_in, const int* in_sizes, int n_in,
                              void* d_out, int out_size)
{
    const float* Q    = (const float*)d_in[0];
    const float* K    = (const float*)d_in[1];
    const float* V    = (const float*)d_in[2];
    const float* mask = (const float*)d_in[3];
    const float* W    = (const float*)d_in[4];
    const float* bias = (const float*)d_in[5];
    float* out        = (float*)d_out;

    // attn smem: (2*128 + 4*64) * 72 bf16 = 36864 elems = 73728 B
    const int attn_smem = (2 * BM + 4 * BN) * PADH * (int)sizeof(__nv_bfloat16);
    cudaFuncSetAttribute(attn_kernel, cudaFuncAttributeMaxDynamicSharedMemorySize,
                         attn_smem);
    // proj smem: (2*128 + 2*64) * 72 bf16 = 27648 elems = 55296 B
    const int proj_smem = (2 * BM + 2 * BN) * PADH * (int)sizeof(__nv_bfloat16);
    cudaFuncSetAttribute(proj_kernel, cudaFuncAttributeMaxDynamicSharedMemorySize,
                         proj_smem);

    dim3 agrid(S_LEN / BM, BATCH * HEADS);        // (16, 32)
    attn_kernel<<<agrid, 256, attn_smem>>>(Q, K, V, mask);

    dim3 pgrid(DMODEL / BN, BATCH * S_LEN / BM);  // (16, 32)
    proj_kernel<<<pgrid, 256, proj_smem>>>(W, bias, out);
}

// round 10
// speedup vs baseline: 4.7533x; 1.6219x over previous
#include <cuda_runtime.h>
#include <cuda_bf16.h>
#include <stdint.h>

#define S_LEN   2048
#define DH      64
#define HEADS   16
#define BATCH   2
#define DMODEL  1024

#define BM      128     // query rows / output rows per CTA
#define BN      64      // key tile / output cols per CTA
#define PADH    72      // bf16 row stride (144B: 16B-aligned, conflict-free ldmatrix)

#define NTOK    (BATCH * S_LEN * DMODEL)   // 4M elements

// Persistent split-bf16 operands (hi + lo, lo = fp32 - bf16(hi))
__device__ __nv_bfloat16 g_Qh[NTOK], g_Ql[NTOK];
__device__ __nv_bfloat16 g_Kh[NTOK], g_Kl[NTOK];
__device__ __nv_bfloat16 g_Vh[NTOK], g_Vl[NTOK];
__device__ __nv_bfloat16 g_Wh[DMODEL * DMODEL], g_Wl[DMODEL * DMODEL];
__device__ __nv_bfloat16 g_xh[NTOK], g_xl[NTOK];   // attention output, split

// ---------------------------------------------------------------------------
// PTX helpers
// ---------------------------------------------------------------------------
__device__ __forceinline__ uint32_t cvta_s(const void* p) {
    return (uint32_t)__cvta_generic_to_shared(p);
}
__device__ __forceinline__ void ldsm_x4(uint32_t* r, uint32_t a) {
    asm volatile("ldmatrix.sync.aligned.m8n8.x4.shared.b16 {%0,%1,%2,%3}, [%4];"
        : "=r"(r[0]), "=r"(r[1]), "=r"(r[2]), "=r"(r[3]) : "r"(a));
}
__device__ __forceinline__ void ldsm_x4t(uint32_t* r, uint32_t a) {
    asm volatile("ldmatrix.sync.aligned.m8n8.x4.trans.shared.b16 {%0,%1,%2,%3}, [%4];"
        : "=r"(r[0]), "=r"(r[1]), "=r"(r[2]), "=r"(r[3]) : "r"(a));
}
__device__ __forceinline__ void mma_bf(float* c, const uint32_t* a, const uint32_t* b) {
    asm volatile("mma.sync.aligned.m16n8k16.row.col.f32.bf16.bf16.f32 "
        "{%0,%1,%2,%3}, {%4,%5,%6,%7}, {%8,%9}, {%0,%1,%2,%3};"
        : "+f"(c[0]), "+f"(c[1]), "+f"(c[2]), "+f"(c[3])
        : "r"(a[0]), "r"(a[1]), "r"(a[2]), "r"(a[3]), "r"(b[0]), "r"(b[1]));
}
__device__ __forceinline__ uint32_t packbf(float x, float y) {
    __nv_bfloat162 h = __floats2bfloat162_rn(x, y);
    return *(uint32_t*)&h;
}
__device__ __forceinline__ void split_pack(float x, float y, uint32_t& hi, uint32_t& lo) {
    float hx = __bfloat162float(__float2bfloat16(x));
    float hy = __bfloat162float(__float2bfloat16(y));
    hi = packbf(hx, hy);
    lo = packbf(x - hx, y - hy);
}
__device__ __forceinline__ void split4_store(__nv_bfloat16* hi, __nv_bfloat16* lo, float4 v) {
    float hx = __bfloat162float(__float2bfloat16(v.x));
    float hy = __bfloat162float(__float2bfloat16(v.y));
    float hz = __bfloat162float(__float2bfloat16(v.z));
    float hw = __bfloat162float(__float2bfloat16(v.w));
    uint2 h2; h2.x = packbf(hx, hy);          h2.y = packbf(hz, hw);
    uint2 l2; l2.x = packbf(v.x-hx, v.y-hy);  l2.y = packbf(v.z-hz, v.w-hw);
    *(uint2*)hi = h2;
    *(uint2*)lo = l2;
}

// ---------------------------------------------------------------------------
// Preprocess: split Q (x0.125), K, V into hi/lo bf16. One float4 per thread.
// ---------------------------------------------------------------------------
__global__ __launch_bounds__(256)
void prep_qkv(const float* __restrict__ Q, const float* __restrict__ K,
              const float* __restrict__ V)
{
    int i = blockIdx.x * 256 + threadIdx.x;       // float4 index, [0, NTOK/4)
    int e = i * 4;
    float4 q = ((const float4*)Q)[i];
    q.x *= 0.125f; q.y *= 0.125f; q.z *= 0.125f; q.w *= 0.125f;
    split4_store(g_Qh + e, g_Ql + e, q);
    split4_store(g_Kh + e, g_Kl + e, ((const float4*)K)[i]);
    split4_store(g_Vh + e, g_Vl + e, ((const float4*)V)[i]);
}
__global__ __launch_bounds__(256)
void prep_w(const float* __restrict__ W)
{
    int i = blockIdx.x * 256 + threadIdx.x;       // [0, DMODEL*DMODEL/4)
    int e = i * 4;
    split4_store(g_Wh + e, g_Wl + e, ((const float4*)W)[i]);
}

// ---------------------------------------------------------------------------
// Flash attention, mma.sync bf16-split, pre-split operands.
// grid (16, 32), 256 thr, 2 CTA/SM. Warp w owns rows [16w,16w+16).
// ---------------------------------------------------------------------------
__global__ __launch_bounds__(256, 2)
void attn_kernel(const float* __restrict__ mask)
{
    extern __shared__ __nv_bfloat16 sb[];
    __nv_bfloat16* sQh = sb;
    __nv_bfloat16* sQl = sQh + BM * PADH;
    __nv_bfloat16* sKh = sQl + BM * PADH;
    __nv_bfloat16* sKl = sKh + BN * PADH;
    __nv_bfloat16* sVh = sKl + BN * PADH;
    __nv_bfloat16* sVl = sVh + BN * PADH;

    const int tid  = threadIdx.x;
    const int warp = tid >> 5;
    const int lane = tid & 31;
    const int g    = lane >> 2;
    const int qd   = lane & 3;
    const int l16  = lane & 15;
    const int mrow = warp * 16;
    const int q0   = blockIdx.x * BM;
    const size_t base = (size_t)blockIdx.y * (S_LEN * DH);

    // ---- load pre-split Q tile (128x64 hi/lo) ----
    #pragma unroll
    for (int it = 0; it < 4; it++) {
        int i = tid + it * 256;                  // [0,1024) uint4 per array
        int r = i >> 3, c8 = (i & 7) * 8;
        size_t off = base + (size_t)(q0 + r) * DH + c8;
        *(uint4*)(sQh + r * PADH + c8) = *(const uint4*)(g_Qh + off);
        *(uint4*)(sQl + r * PADH + c8) = *(const uint4*)(g_Ql + off);
    }

    const uint32_t qh32 = cvta_s(sQh), ql32 = cvta_s(sQl);
    const uint32_t kh32 = cvta_s(sKh), kl32 = cvta_s(sKl);
    const uint32_t vh32 = cvta_s(sVh), vl32 = cvta_s(sVl);

    float o[8][4];
    #pragma unroll
    for (int n = 0; n < 8; n++)
        #pragma unroll
        for (int c = 0; c < 4; c++) o[n][c] = 0.0f;
    float m0r = -1e30f, m1r = -1e30f, l0r = 0.0f, l1r = 0.0f;

    const float* mk0 = mask + (size_t)(q0 + mrow + g) * S_LEN;
    const float* mk1 = mk0 + 8 * S_LEN;
    const int t8 = lane >> 3;      // ldsm x4 tile index

    for (int kt = 0; kt < S_LEN; kt += BN) {
        // ---- load pre-split K,V tiles ----
        #pragma unroll
        for (int it = 0; it < 2; it++) {
            int i = tid + it * 256;              // [0,512) uint4 per array
            int r = i >> 3, c8 = (i & 7) * 8;
            size_t off = base + (size_t)(kt + r) * DH + c8;
            *(uint4*)(sKh + r * PADH + c8) = *(const uint4*)(g_Kh + off);
            *(uint4*)(sKl + r * PADH + c8) = *(const uint4*)(g_Kl + off);
            *(uint4*)(sVh + r * PADH + c8) = *(const uint4*)(g_Vh + off);
            *(uint4*)(sVl + r * PADH + c8) = *(const uint4*)(g_Vl + off);
        }
        __syncthreads();

        // ---- S = Q @ K^T (3-product split, paired-B x4 loads) ----
        float s[8][4];
        #pragma unroll
        for (int n = 0; n < 8; n++)
            #pragma unroll
            for (int c = 0; c < 4; c++) s[n][c] = 0.0f;

        #pragma unroll
        for (int k = 0; k < 4; k++) {
            uint32_t ah[4], al[4];
            uint32_t ao = (uint32_t)(((mrow + l16) * PADH + k * 16 + (lane >> 4) * 8) * 2);
            ldsm_x4(ah, qh32 + ao);
            ldsm_x4(al, ql32 + ao);
            #pragma unroll
            for (int np = 0; np < 4; np++) {
                uint32_t bh[4], bl[4];
                uint32_t bo = (uint32_t)((((2 * np + (t8 >> 1)) * 8 + (lane & 7)) * PADH
                                          + k * 16 + (t8 & 1) * 8) * 2);
                ldsm_x4(bh, kh32 + bo);
                ldsm_x4(bl, kl32 + bo);
                mma_bf(s[2*np  ], ah, bh);     mma_bf(s[2*np  ], ah, bl);     mma_bf(s[2*np  ], al, bh);
                mma_bf(s[2*np+1], ah, bh + 2); mma_bf(s[2*np+1], ah, bl + 2); mma_bf(s[2*np+1], al, bh + 2);
            }
        }

        // ---- add mask ----
        #pragma unroll
        for (int n = 0; n < 8; n++) {
            float2 a = *(const float2*)(mk0 + kt + n * 8 + qd * 2);
            float2 b = *(const float2*)(mk1 + kt + n * 8 + qd * 2);
            s[n][0] += a.x; s[n][1] += a.y; s[n][2] += b.x; s[n][3] += b.y;
        }

        // ---- online softmax ----
        float mx0 = -1e30f, mx1 = -1e30f;
        #pragma unroll
        for (int n = 0; n < 8; n++) {
            mx0 = fmaxf(mx0, fmaxf(s[n][0], s[n][1]));
            mx1 = fmaxf(mx1, fmaxf(s[n][2], s[n][3]));
        }
        mx0 = fmaxf(mx0, __shfl_xor_sync(0xffffffffu, mx0, 1));
        mx0 = fmaxf(mx0, __shfl_xor_sync(0xffffffffu, mx0, 2));
        mx1 = fmaxf(mx1, __shfl_xor_sync(0xffffffffu, mx1, 1));
        mx1 = fmaxf(mx1, __shfl_xor_sync(0xffffffffu, mx1, 2));
        float mn0 = fmaxf(m0r, mx0), mn1 = fmaxf(m1r, mx1);
        float c0 = __expf(m0r - mn0), c1 = __expf(m1r - mn1);
        m0r = mn0; m1r = mn1;

        float s0 = 0.0f, s1 = 0.0f;
        #pragma unroll
        for (int n = 0; n < 8; n++) {
            s[n][0] = __expf(s[n][0] - mn0); s[n][1] = __expf(s[n][1] - mn0);
            s[n][2] = __expf(s[n][2] - mn1); s[n][3] = __expf(s[n][3] - mn1);
            s0 += s[n][0] + s[n][1];
            s1 += s[n][2] + s[n][3];
        }
        s0 += __shfl_xor_sync(0xffffffffu, s0, 1);
        s0 += __shfl_xor_sync(0xffffffffu, s0, 2);
        s1 += __shfl_xor_sync(0xffffffffu, s1, 1);
        s1 += __shfl_xor_sync(0xffffffffu, s1, 2);
        l0r = l0r * c0 + s0;
        l1r = l1r * c1 + s1;

        #pragma unroll
        for (int n = 0; n < 8; n++) {
            o[n][0] *= c0; o[n][1] *= c0; o[n][2] *= c1; o[n][3] *= c1;
        }

        // ---- O += P @ V (P split in regs, paired-B x4 trans loads) ----
        #pragma unroll
        for (int k = 0; k < 4; k++) {
            uint32_t ph[4], pl[4];
            split_pack(s[2*k  ][0], s[2*k  ][1], ph[0], pl[0]);
            split_pack(s[2*k  ][2], s[2*k  ][3], ph[1], pl[1]);
            split_pack(s[2*k+1][0], s[2*k+1][1], ph[2], pl[2]);
            split_pack(s[2*k+1][2], s[2*k+1][3], ph[3], pl[3]);
            #pragma unroll
            for (int np = 0; np < 4; np++) {
                uint32_t bh[4], bl[4];
                uint32_t bo = (uint32_t)(((k * 16 + (t8 & 1) * 8 + (lane & 7)) * PADH
                                          + (2 * np + (t8 >> 1)) * 8) * 2);
                ldsm_x4t(bh, vh32 + bo);
                ldsm_x4t(bl, vl32 + bo);
                mma_bf(o[2*np  ], ph, bh);     mma_bf(o[2*np  ], ph, bl);     mma_bf(o[2*np  ], pl, bh);
                mma_bf(o[2*np+1], ph, bh + 2); mma_bf(o[2*np+1], ph, bl + 2); mma_bf(o[2*np+1], pl, bh + 2);
            }
        }
        __syncthreads();   // protect K/V tiles before next iteration
    }

    // ---- epilogue: O /= l, split-store to g_xh/g_xl ----
    float i0 = 1.0f / l0r, i1 = 1.0f / l1r;
    size_t r0off = base + (size_t)(q0 + mrow + g) * DH;
    size_t r1off = r0off + 8 * DH;
    #pragma unroll
    for (int n = 0; n < 8; n++) {
        uint32_t h, l;
        split_pack(o[n][0] * i0, o[n][1] * i0, h, l);
        *(uint32_t*)(g_xh + r0off + n * 8 + qd * 2) = h;
        *(uint32_t*)(g_xl + r0off + n * 8 + qd * 2) = l;
        split_pack(o[n][2] * i1, o[n][3] * i1, h, l);
        *(uint32_t*)(g_xh + r1off + n * 8 + qd * 2) = h;
        *(uint32_t*)(g_xl + r1off + n * 8 + qd * 2) = l;
    }
}

// ---------------------------------------------------------------------------
// Projection: out[4096,1024] = x @ W^T + b, pre-split operands.
// grid (16, 32), 256 threads, 2 CTA/SM.
// ---------------------------------------------------------------------------
__global__ __launch_bounds__(256, 2)
void proj_kernel(const float* __restrict__ bias, float* __restrict__ out)
{
    extern __shared__ __nv_bfloat16 sb[];
    __nv_bfloat16* sXh = sb;
    __nv_bfloat16* sXl = sXh + BM * PADH;
    __nv_bfloat16* sWh = sXl + BM * PADH;
    __nv_bfloat16* sWl = sWh + BN * PADH;

    const int tid  = threadIdx.x;
    const int warp = tid >> 5;
    const int lane = tid & 31;
    const int g    = lane >> 2;
    const int qd   = lane & 3;
    const int l16  = lane & 15;
    const int mrow = warp * 16;
    const int n0   = blockIdx.x * BN;
    const int m0   = blockIdx.y * BM;
    const int t8   = lane >> 3;

    const uint32_t xh32 = cvta_s(sXh), xl32 = cvta_s(sXl);
    const uint32_t wh32 = cvta_s(sWh), wl32 = cvta_s(sWl);

    float o[8][4];
    #pragma unroll
    for (int n = 0; n < 8; n++)
        #pragma unroll
        for (int c = 0; c < 4; c++) o[n][c] = 0.0f;

    for (int kt = 0; kt < DMODEL; kt += 64) {
        #pragma unroll
        for (int it = 0; it < 4; it++) {
            int i = tid + it * 256;              // [0,1024) uint4 per array
            int r = i >> 3, c8 = (i & 7) * 8;
            size_t off = (size_t)(m0 + r) * DMODEL + kt + c8;
            *(uint4*)(sXh + r * PADH + c8) = *(const uint4*)(g_xh + off);
            *(uint4*)(sXl + r * PADH + c8) = *(const uint4*)(g_xl + off);
        }
        #pragma unroll
        for (int it = 0; it < 2; it++) {
            int i = tid + it * 256;              // [0,512)
            int r = i >> 3, c8 = (i & 7) * 8;
            size_t off = (size_t)(n0 + r) * DMODEL + kt + c8;
            *(uint4*)(sWh + r * PADH + c8) = *(const uint4*)(g_Wh + off);
            *(uint4*)(sWl + r * PADH + c8) = *(const uint4*)(g_Wl + off);
        }
        __syncthreads();

        #pragma unroll
        for (int k = 0; k < 4; k++) {
            uint32_t ah[4], al[4];
            uint32_t ao = (uint32_t)(((mrow + l16) * PADH + k * 16 + (lane >> 4) * 8) * 2);
            ldsm_x4(ah, xh32 + ao);
            ldsm_x4(al, xl32 + ao);
            #pragma unroll
            for (int np = 0; np < 4; np++) {
                uint32_t bh[4], bl[4];
                uint32_t bo = (uint32_t)((((2 * np + (t8 >> 1)) * 8 + (lane & 7)) * PADH
                                          + k * 16 + (t8 & 1) * 8) * 2);
                ldsm_x4(bh, wh32 + bo);
                ldsm_x4(bl, wl32 + bo);
                mma_bf(o[2*np  ], ah, bh);     mma_bf(o[2*np  ], ah, bl);     mma_bf(o[2*np  ], al, bh);
                mma_bf(o[2*np+1], ah, bh + 2); mma_bf(o[2*np+1], ah, bl + 2); mma_bf(o[2*np+1], al, bh + 2);
            }
        }
        __syncthreads();
    }

    float* od0 = out + (size_t)(m0 + mrow + g) * DMODEL + n0;
    float* od1 = od0 + 8 * DMODEL;
    #pragma unroll
    for (int n = 0; n < 8; n++) {
        float2 bv = *(const float2*)(bias + n0 + n * 8 + qd * 2);
        float2 a; a.x = o[n][0] + bv.x; a.y = o[n][1] + bv.y;
        float2 b; b.x = o[n][2] + bv.x; b.y = o[n][3] + bv.y;
        *(float2*)(od0 + n * 8 + qd * 2) = a;
        *(float2*)(od1 + n * 8 + qd * 2) = b;
    }
}

// ---------------------------------------------------------------------------
extern "C" void kernel_launch(void* const* d_in, const int* in_sizes, int n_in,
                              void* d_out, int out_size)
{
    const float* Q    = (const float*)d_in[0];
    const float* K    = (const float*)d_in[1];
    const float* V    = (const float*)d_in[2];
    const float* mask = (const float*)d_in[3];
    const float* W    = (const float*)d_in[4];
    const float* bias = (const float*)d_in[5];
    float* out        = (float*)d_out;

    prep_qkv<<<NTOK / 4 / 256, 256>>>(Q, K, V);            // 4096 blocks
    prep_w<<<DMODEL * DMODEL / 4 / 256, 256>>>(W);         // 1024 blocks

    const int attn_smem = (2 * BM + 4 * BN) * PADH * (int)sizeof(__nv_bfloat16); // 73728
    cudaFuncSetAttribute(attn_kernel, cudaFuncAttributeMaxDynamicSharedMemorySize,
                         attn_smem);
    const int proj_smem = (2 * BM + 2 * BN) * PADH * (int)sizeof(__nv_bfloat16); // 55296
    cudaFuncSetAttribute(proj_kernel, cudaFuncAttributeMaxDynamicSharedMemorySize,
                         proj_smem);

    dim3 agrid(S_LEN / BM, BATCH * HEADS);        // (16, 32)
    attn_kernel<<<agrid, 256, attn_smem>>>(mask);

    dim3 pgrid(DMODEL / BN, BATCH * S_LEN / BM);  // (16, 32)
    proj_kernel<<<pgrid, 256, proj_smem>>>(bias, out);
}